// round 1
// baseline (speedup 1.0000x reference)
#include <cuda_runtime.h>
#include <math.h>

#define B 64
#define H 80
#define W 80
#define C 80
#define CP 84
#define K 100
#define CAND_MAX 131072
#define EQCAP 256

// Scratch (no allocation allowed in kernel_launch): per-batch candidate lists.
__device__ float g_cval[B][CAND_MAX];
__device__ int   g_cidx[B][CAND_MAX];
__device__ int   g_cnt[B];

__global__ void reset_kernel() {
    if (threadIdx.x < B) g_cnt[threadIdx.x] = 0;
}

// One thread handles 4 consecutive channels at one (b,i,j).
// total threads = B*H*W*(C/4) = 8,192,000 (multiple of 256; warps never cross batch).
__global__ void peaks_kernel(const float* __restrict__ y) {
    int t = blockIdx.x * blockDim.x + threadIdx.x;
    int cg   = t % (C / 4);
    int s    = t / (C / 4);
    int j    = s % W;
    int rest = s / W;
    int i    = rest % H;
    int b    = rest / H;
    int c0   = cg * 4;

    const float* base = y + ((size_t)((b * H + i) * W + j)) * CP + c0;
    float4 v = *(const float4*)base;
    float4 m = v;

    #pragma unroll
    for (int di = -1; di <= 1; ++di) {
        int ii = i + di;
        if (ii < 0 || ii >= H) continue;
        #pragma unroll
        for (int dj = -1; dj <= 1; ++dj) {
            if (di == 0 && dj == 0) continue;
            int jj = j + dj;
            if (jj < 0 || jj >= W) continue;
            float4 nb = *(const float4*)(base + (di * W + dj) * CP);
            m.x = fmaxf(m.x, nb.x);
            m.y = fmaxf(m.y, nb.y);
            m.z = fmaxf(m.z, nb.z);
            m.w = fmaxf(m.w, nb.w);
        }
    }

    float vv[4] = {v.x, v.y, v.z, v.w};
    float mm[4] = {m.x, m.y, m.z, m.w};
    float cv[4]; int ci[4]; int cnt = 0;
    int sidx = (i * W + j) * C + c0;
    #pragma unroll
    for (int q = 0; q < 4; ++q) {
        // keep = hmax * (hm == hmax): nonzero peak iff value equals window max; only >0 can reach top-K
        if (vv[q] == mm[q] && vv[q] > 0.0f) {
            cv[cnt] = vv[q];
            ci[cnt] = sidx + q;
            cnt++;
        }
    }

    // Warp-aggregated append (b is warp-uniform by construction)
    int lane = threadIdx.x & 31;
    int incl = cnt;
    #pragma unroll
    for (int d = 1; d < 32; d <<= 1) {
        int o = __shfl_up_sync(0xffffffffu, incl, d);
        if (lane >= d) incl += o;
    }
    int total = __shfl_sync(0xffffffffu, incl, 31);
    if (total > 0) {
        int basep = 0;
        if (lane == 31) basep = atomicAdd(&g_cnt[b], total);
        basep = __shfl_sync(0xffffffffu, basep, 31);
        int off = basep + incl - cnt;
        for (int q = 0; q < cnt; ++q) {
            int p = off + q;
            if (p < CAND_MAX) {
                g_cval[b][p] = cv[q];
                g_cidx[b][p] = ci[q];
            }
        }
    }
}

// One block per batch: exact radix-select of the K-th largest key, tie-break
// by smallest flat index (matches jax stable argsort of -score), rank sort,
// gather + write outputs.
__global__ void select_kernel(const float* __restrict__ y, float* __restrict__ out) {
    int b   = blockIdx.x;
    int tid = threadIdx.x;
    int n   = g_cnt[b];
    if (n > CAND_MAX) n = CAND_MAX;

    __shared__ int      hist[256];
    __shared__ unsigned s_prefix;
    __shared__ int      s_remain;
    __shared__ float    aval[K];
    __shared__ int      aidx[K];
    __shared__ int      eidx[EQCAP];
    __shared__ int      cntA, cntE;

    float* score_out = out;
    float* k_out     = out + B * K;
    float* c_out     = out + 2 * B * K;
    float* w_out     = out + 4 * B * K;

    unsigned T = 0;   // selection threshold key (exact K-th largest)
    int needEq = 0;   // how many key==T items to take (smallest indices first)

    if (n >= K) {
        unsigned prefix = 0;
        int remain = K;
        for (int shift = 24; shift >= 0; shift -= 8) {
            hist[tid] = 0;
            __syncthreads();
            unsigned mask_hi = (shift == 24) ? 0u : (0xFFFFFFFFu << (shift + 8));
            for (int p = tid; p < n; p += blockDim.x) {
                unsigned key = __float_as_uint(g_cval[b][p]);
                if ((key & mask_hi) == prefix) {
                    int bin = (key >> shift) & 0xFF;
                    unsigned am  = __activemask();
                    unsigned grp = __match_any_sync(am, bin);
                    int leader   = __ffs(grp) - 1;
                    if ((threadIdx.x & 31) == leader)
                        atomicAdd(&hist[bin], __popc(grp));
                }
            }
            __syncthreads();
            if (tid == 0) {
                int acc = 0, sel = 0;
                for (int v2 = 255; v2 >= 0; --v2) {
                    if (acc + hist[v2] >= remain) { sel = v2; break; }
                    acc += hist[v2];
                }
                s_prefix = prefix | ((unsigned)sel << shift);
                s_remain = remain - acc;
            }
            __syncthreads();
            prefix = s_prefix;
            remain = s_remain;
            __syncthreads();
        }
        T = prefix;
        needEq = remain;
    } else {
        T = 0;       // all positive keys are > 0 -> take everything
        needEq = 0;
    }

    if (tid == 0) { cntA = 0; cntE = 0; }
    __syncthreads();

    for (int p = tid; p < n; p += blockDim.x) {
        float fv = g_cval[b][p];
        unsigned key = __float_as_uint(fv);
        if (key > T) {
            int q = atomicAdd(&cntA, 1);
            if (q < K) { aval[q] = fv; aidx[q] = g_cidx[b][p]; }
        } else if (key == T) {
            int q = atomicAdd(&cntE, 1);
            if (q < EQCAP) eidx[q] = g_cidx[b][p];
        }
    }
    __syncthreads();

    int mA = cntA; if (mA > K) mA = K;
    int nE = cntE; if (nE > EQCAP) nE = EQCAP;
    int take = K - mA;
    if (take > needEq) take = needEq;
    if (take > nE) take = nE;

    // pick the 'take' equal-key items with the smallest indices
    for (int e = tid; e < nE; e += blockDim.x) {
        int mine = eidx[e];
        int rank = 0;
        for (int q = 0; q < nE; ++q) rank += (eidx[q] < mine);
        if (rank < take) {
            aval[mA + rank] = __uint_as_float(T);
            aidx[mA + rank] = mine;
        }
    }
    __syncthreads();

    int M = mA + take;   // == K in normal operation

    if (tid < M) {
        unsigned mykey = __float_as_uint(aval[tid]);
        int myidx = aidx[tid];
        int r = 0;
        for (int q = 0; q < M; ++q) {
            unsigned kq = __float_as_uint(aval[q]);
            r += (kq > mykey) || (kq == mykey && aidx[q] < myidx);
        }
        int fi  = myidx;
        int kk  = fi % C;
        int rem = fi / C;
        int jj  = rem % W;
        int ii  = rem / W;
        const float* p = y + ((size_t)((b * H + ii) * W + jj)) * CP;
        float whx = 4.0f * (expf(p[C])     - 1.0f);
        float why = 4.0f * (expf(p[C + 1]) - 1.0f);
        float cx  = 4.0f * (float)jj + p[C + 2];
        float cy  = 4.0f * (float)ii + p[C + 3];

        score_out[b * K + r] = aval[tid];
        k_out[b * K + r]     = (float)kk;
        c_out[(b * K + r) * 2 + 0] = cx;
        c_out[(b * K + r) * 2 + 1] = cy;
        w_out[(b * K + r) * 2 + 0] = whx;
        w_out[(b * K + r) * 2 + 1] = why;
    }

    // pad (degenerate case only)
    for (int r = M + tid; r < K; r += blockDim.x) {
        score_out[b * K + r] = 0.0f;
        k_out[b * K + r]     = 0.0f;
        c_out[(b * K + r) * 2 + 0] = 0.0f;
        c_out[(b * K + r) * 2 + 1] = 0.0f;
        w_out[(b * K + r) * 2 + 0] = 0.0f;
        w_out[(b * K + r) * 2 + 1] = 0.0f;
    }
}

extern "C" void kernel_launch(void* const* d_in, const int* in_sizes, int n_in,
                              void* d_out, int out_size) {
    const float* yp = (const float*)d_in[0];
    float* out = (float*)d_out;

    reset_kernel<<<1, 64>>>();

    int total = B * H * W * (C / 4);     // 8,192,000
    peaks_kernel<<<total / 256, 256>>>(yp);

    select_kernel<<<B, 256>>>(yp, out);
}

// round 2
// speedup vs baseline: 1.7943x; 1.7943x over previous
#include <cuda_runtime.h>
#include <math.h>

#define B 64
#define H 80
#define W 80
#define C 80
#define CP 84
#define K 100
#define CAND_MAX 131072
#define EQCAP 256

// Scratch: per-batch packed candidates (key<<32 | idx). Counters padded to one
// per 128B cache line to avoid LTS same-line serialization.
__device__ unsigned long long g_cand[B][CAND_MAX];
__device__ int g_cnt[B * 32];

// One thread handles 4 consecutive channels at one (b,i,j).
// total threads = B*H*W*(C/4) = 8,192,000; each 256-thread block has uniform b.
__global__ void peaks_kernel(const float* __restrict__ y) {
    __shared__ int s_total;
    __shared__ int s_base;
    if (threadIdx.x == 0) s_total = 0;
    __syncthreads();

    int t = blockIdx.x * blockDim.x + threadIdx.x;
    int cg   = t % (C / 4);
    int s    = t / (C / 4);
    int j    = s % W;
    int rest = s / W;
    int i    = rest % H;
    int b    = rest / H;
    int c0   = cg * 4;

    const float* base = y + ((size_t)((b * H + i) * W + j)) * CP + c0;
    float4 v = *(const float4*)base;
    float4 m = v;

    #pragma unroll
    for (int di = -1; di <= 1; ++di) {
        int ii = i + di;
        if (ii < 0 || ii >= H) continue;
        #pragma unroll
        for (int dj = -1; dj <= 1; ++dj) {
            if (di == 0 && dj == 0) continue;
            int jj = j + dj;
            if (jj < 0 || jj >= W) continue;
            float4 nb = *(const float4*)(base + (di * W + dj) * CP);
            m.x = fmaxf(m.x, nb.x);
            m.y = fmaxf(m.y, nb.y);
            m.z = fmaxf(m.z, nb.z);
            m.w = fmaxf(m.w, nb.w);
        }
    }

    float vv[4] = {v.x, v.y, v.z, v.w};
    float mm[4] = {m.x, m.y, m.z, m.w};
    unsigned long long pk[4]; int cnt = 0;
    int sidx = (i * W + j) * C + c0;
    #pragma unroll
    for (int q = 0; q < 4; ++q) {
        // keep = hmax * (hm == hmax): peak iff value equals 3x3 window max; only >0 can reach top-K
        if (vv[q] == mm[q] && vv[q] > 0.0f) {
            pk[cnt] = ((unsigned long long)__float_as_uint(vv[q]) << 32)
                      | (unsigned)(sidx + q);
            cnt++;
        }
    }

    // warp-inclusive prefix of cnt
    int lane = threadIdx.x & 31;
    int incl = cnt;
    #pragma unroll
    for (int d = 1; d < 32; d <<= 1) {
        int o = __shfl_up_sync(0xffffffffu, incl, d);
        if (lane >= d) incl += o;
    }
    int wtotal = __shfl_sync(0xffffffffu, incl, 31);
    int wbase = 0;
    if (lane == 31 && wtotal > 0) wbase = atomicAdd(&s_total, wtotal);
    wbase = __shfl_sync(0xffffffffu, wbase, 31);
    __syncthreads();

    if (threadIdx.x == 0) {
        int bt = s_total;
        s_base = (bt > 0) ? atomicAdd(&g_cnt[b * 32], bt) : 0;
    }
    __syncthreads();

    int off = s_base + wbase + incl - cnt;
    for (int q = 0; q < cnt; ++q) {
        int p = off + q;
        if (p < CAND_MAX) g_cand[b][p] = pk[q];
    }
}

// One block per batch: exact radix-select of the K-th largest key, ties broken
// by smallest flat index (jax stable argsort of -score), rank sort, gather.
__global__ void select_kernel(const float* __restrict__ y, float* __restrict__ out) {
    int b   = blockIdx.x;
    int tid = threadIdx.x;
    int n   = g_cnt[b * 32];
    if (n > CAND_MAX) n = CAND_MAX;

    __shared__ int      hist[256];
    __shared__ unsigned s_prefix;
    __shared__ int      s_remain;
    __shared__ float    aval[K];
    __shared__ int      aidx[K];
    __shared__ int      eidx[EQCAP];
    __shared__ int      cntA, cntE;

    float* score_out = out;
    float* k_out     = out + B * K;
    float* c_out     = out + 2 * B * K;
    float* w_out     = out + 4 * B * K;

    unsigned T = 0;
    int needEq = 0;

    if (n >= K) {
        unsigned prefix = 0;
        int remain = K;
        for (int shift = 24; shift >= 0; shift -= 8) {
            if (tid < 256) hist[tid] = 0;
            __syncthreads();
            unsigned mask_hi = (shift == 24) ? 0u : (0xFFFFFFFFu << (shift + 8));
            for (int p = tid; p < n; p += blockDim.x) {
                unsigned key = (unsigned)(g_cand[b][p] >> 32);
                if ((key & mask_hi) == prefix) {
                    int bin = (key >> shift) & 0xFF;
                    unsigned am  = __activemask();
                    unsigned grp = __match_any_sync(am, bin);
                    int leader   = __ffs(grp) - 1;
                    if ((threadIdx.x & 31) == leader)
                        atomicAdd(&hist[bin], __popc(grp));
                }
            }
            __syncthreads();
            if (tid == 0) {
                int acc = 0, sel = 0;
                for (int v2 = 255; v2 >= 0; --v2) {
                    if (acc + hist[v2] >= remain) { sel = v2; break; }
                    acc += hist[v2];
                }
                s_prefix = prefix | ((unsigned)sel << shift);
                s_remain = remain - acc;
            }
            __syncthreads();
            prefix = s_prefix;
            remain = s_remain;
            __syncthreads();
        }
        T = prefix;
        needEq = remain;
    }

    if (tid == 0) { cntA = 0; cntE = 0; }
    __syncthreads();

    for (int p = tid; p < n; p += blockDim.x) {
        unsigned long long pk = g_cand[b][p];
        unsigned key = (unsigned)(pk >> 32);
        if (key > T) {
            int q = atomicAdd(&cntA, 1);
            if (q < K) { aval[q] = __uint_as_float(key); aidx[q] = (int)(unsigned)pk; }
        } else if (key == T) {
            int q = atomicAdd(&cntE, 1);
            if (q < EQCAP) eidx[q] = (int)(unsigned)pk;
        }
    }
    __syncthreads();

    int mA = cntA; if (mA > K) mA = K;
    int nE = cntE; if (nE > EQCAP) nE = EQCAP;
    int take = K - mA;
    if (take > needEq) take = needEq;
    if (take > nE) take = nE;

    // equal-key items: take the 'take' smallest indices
    for (int e = tid; e < nE; e += blockDim.x) {
        int mine = eidx[e];
        int rank = 0;
        for (int q = 0; q < nE; ++q) rank += (eidx[q] < mine);
        if (rank < take) {
            aval[mA + rank] = __uint_as_float(T);
            aidx[mA + rank] = mine;
        }
    }
    __syncthreads();

    int M = mA + take;   // == K in normal operation

    if (tid < M) {
        unsigned mykey = __float_as_uint(aval[tid]);
        int myidx = aidx[tid];
        int r = 0;
        for (int q = 0; q < M; ++q) {
            unsigned kq = __float_as_uint(aval[q]);
            r += (kq > mykey) || (kq == mykey && aidx[q] < myidx);
        }
        int fi  = myidx;
        int kk  = fi % C;
        int rem = fi / C;
        int jj  = rem % W;
        int ii  = rem / W;
        const float* p = y + ((size_t)((b * H + ii) * W + jj)) * CP;
        float whx = 4.0f * (expf(p[C])     - 1.0f);
        float why = 4.0f * (expf(p[C + 1]) - 1.0f);
        float cx  = 4.0f * (float)jj + p[C + 2];
        float cy  = 4.0f * (float)ii + p[C + 3];

        score_out[b * K + r] = aval[tid];
        k_out[b * K + r]     = (float)kk;
        c_out[(b * K + r) * 2 + 0] = cx;
        c_out[(b * K + r) * 2 + 1] = cy;
        w_out[(b * K + r) * 2 + 0] = whx;
        w_out[(b * K + r) * 2 + 1] = why;
    }

    // pad (degenerate case only)
    for (int r = M + tid; r < K; r += blockDim.x) {
        score_out[b * K + r] = 0.0f;
        k_out[b * K + r]     = 0.0f;
        c_out[(b * K + r) * 2 + 0] = 0.0f;
        c_out[(b * K + r) * 2 + 1] = 0.0f;
        w_out[(b * K + r) * 2 + 0] = 0.0f;
        w_out[(b * K + r) * 2 + 1] = 0.0f;
    }

    // reset counter for the next graph replay (globals are zero-init on load)
    __syncthreads();
    if (tid == 0) g_cnt[b * 32] = 0;
}

extern "C" void kernel_launch(void* const* d_in, const int* in_sizes, int n_in,
                              void* d_out, int out_size) {
    const float* yp = (const float*)d_in[0];
    float* out = (float*)d_out;

    int total = B * H * W * (C / 4);     // 8,192,000 threads
    peaks_kernel<<<total / 256, 256>>>(yp);
    select_kernel<<<B, 512>>>(yp, out);
}

// round 3
// speedup vs baseline: 1.8327x; 1.0214x over previous
#include <cuda_runtime.h>
#include <math.h>

#define B 64
#define H 80
#define W 80
#define C 80
#define CP 84
#define K 100
#define CAND_MAX 131072
#define EQCAP 2048
#define SELCAP 128
#define SLICES 4

// Scratch. pk = (float_bits(score) << 32) | ~sidx  -> plain u64 '>' gives
// (score desc, idx asc), matching jax stable argsort of -score.
__device__ unsigned long long g_cand[B][CAND_MAX];
__device__ int g_hist[B][65536];
__device__ unsigned long long g_sel[B][SELCAP];
__device__ unsigned long long g_eq[B][EQCAP];
__device__ int g_cnt[B * 32];
__device__ int g_selcnt[B * 32];
__device__ int g_eqcnt[B * 32];
__device__ int g_tbin[B * 32];

// ---------------------------------------------------------------------------
// K1: 3x3 NMS peaks. One thread = 4 rows x 4 channels at one column j.
// Separable max: 18 float4 loads per 16 outputs (vs 36 naive).
// threads = B * (H/4) * W * (C/4) = 2,048,000. 32000 per batch (mult of 256).
__global__ void peaks_kernel(const float* __restrict__ y) {
    __shared__ int s_total;
    __shared__ int s_base;
    if (threadIdx.x == 0) s_total = 0;
    __syncthreads();

    int t  = blockIdx.x * blockDim.x + threadIdx.x;
    int cg = t % (C / 4);
    int j  = (t / (C / 4)) % W;
    int iq = (t / (W * C / 4)) % (H / 4);
    int b  = t / ((H / 4) * W * (C / 4));
    int c0 = cg * 4;
    int i0 = iq * 4;

    const float NEGF = __int_as_float(0xff800000);
    const size_t rowS = (size_t)W * CP;
    const float* bbase = y + (size_t)b * H * rowS + c0;

    float4 m[4];
    float4 v[4];
    #pragma unroll
    for (int r = 0; r < 4; ++r) m[r] = make_float4(NEGF, NEGF, NEGF, NEGF);

    #pragma unroll
    for (int dj = -1; dj <= 1; ++dj) {
        int jj = j + dj;
        bool jok = (jj >= 0) && (jj < W);
        float4 row[6];
        #pragma unroll
        for (int r6 = 0; r6 < 6; ++r6) {
            int ii = i0 - 1 + r6;
            bool ok = jok && (ii >= 0) && (ii < H);
            row[r6] = ok ? *(const float4*)(bbase + (size_t)ii * rowS + (size_t)jj * CP)
                         : make_float4(NEGF, NEGF, NEGF, NEGF);
        }
        #pragma unroll
        for (int r = 0; r < 4; ++r) {
            m[r].x = fmaxf(m[r].x, fmaxf(fmaxf(row[r].x, row[r+1].x), row[r+2].x));
            m[r].y = fmaxf(m[r].y, fmaxf(fmaxf(row[r].y, row[r+1].y), row[r+2].y));
            m[r].z = fmaxf(m[r].z, fmaxf(fmaxf(row[r].z, row[r+1].z), row[r+2].z));
            m[r].w = fmaxf(m[r].w, fmaxf(fmaxf(row[r].w, row[r+1].w), row[r+2].w));
        }
        if (dj == 0) {
            #pragma unroll
            for (int r = 0; r < 4; ++r) v[r] = row[r + 1];
        }
    }

    bool pr[4][4];
    int cnt = 0;
    #pragma unroll
    for (int r = 0; r < 4; ++r) {
        float vr[4] = {v[r].x, v[r].y, v[r].z, v[r].w};
        float mr[4] = {m[r].x, m[r].y, m[r].z, m[r].w};
        #pragma unroll
        for (int q = 0; q < 4; ++q) {
            bool p = (vr[q] == mr[q]) && (vr[q] > 0.0f);
            pr[r][q] = p;
            cnt += p ? 1 : 0;
        }
    }

    // warp prefix + one block-level global atomic
    int lane = threadIdx.x & 31;
    int incl = cnt;
    #pragma unroll
    for (int d = 1; d < 32; d <<= 1) {
        int o = __shfl_up_sync(0xffffffffu, incl, d);
        if (lane >= d) incl += o;
    }
    int wtotal = __shfl_sync(0xffffffffu, incl, 31);
    int wbase = 0;
    if (lane == 31 && wtotal > 0) wbase = atomicAdd(&s_total, wtotal);
    wbase = __shfl_sync(0xffffffffu, wbase, 31);
    __syncthreads();
    if (threadIdx.x == 0) {
        int bt = s_total;
        s_base = (bt > 0) ? atomicAdd(&g_cnt[b * 32], bt) : 0;
    }
    __syncthreads();

    if (cnt > 0) {
        int off = s_base + wbase + incl - cnt;
        #pragma unroll
        for (int r = 0; r < 4; ++r) {
            float vr[4] = {v[r].x, v[r].y, v[r].z, v[r].w};
            #pragma unroll
            for (int q = 0; q < 4; ++q) {
                if (pr[r][q]) {
                    if (off < CAND_MAX) {
                        unsigned key = __float_as_uint(vr[q]);
                        unsigned sidx = (unsigned)(((i0 + r) * W + j) * C + c0 + q);
                        g_cand[b][off] = ((unsigned long long)key << 32) | (unsigned)(~sidx);
                        atomicAdd(&g_hist[b][key >> 16], 1);
                    }
                    off++;
                }
            }
        }
    }
}

// ---------------------------------------------------------------------------
// K2: per-batch threshold bin from histogram (exact K-th), then zero the hist.
__global__ void threshold_kernel() {
    int b = blockIdx.x;
    int tid = threadIdx.x;             // 256 threads
    int* hb = g_hist[b];
    int base = tid * 256;

    __shared__ int sums[256];
    __shared__ int above[256];

    int s = 0;
    #pragma unroll 8
    for (int i = 0; i < 256; i += 4) {
        int4 h4 = *(const int4*)&hb[base + i];
        s += h4.x + h4.y + h4.z + h4.w;
    }
    sums[tid] = s;
    __syncthreads();

    if (tid == 0) {
        int acc = 0;
        for (int t2 = 255; t2 >= 0; --t2) { above[t2] = acc; acc += sums[t2]; }
        g_tbin[b * 32] = -1;           // default: take everything (n < K case)
    }
    __syncthreads();

    if (above[tid] < K && above[tid] + sums[tid] >= K) {
        int acc = above[tid];
        for (int i = 255; i >= 0; --i) {
            int h = hb[base + i];
            if (acc + h >= K) { g_tbin[b * 32] = base + i; break; }
            acc += h;
        }
    }
    __syncthreads();

    int4 z = make_int4(0, 0, 0, 0);
    #pragma unroll 8
    for (int i = 0; i < 256; i += 4) *(int4*)&hb[base + i] = z;
}

// ---------------------------------------------------------------------------
// K3: one scan of candidates -> above-threshold list (<K) + threshold-bin list.
__global__ void compact_kernel() {
    int bs = blockIdx.x;
    int b  = bs / SLICES;
    int sl = bs % SLICES;
    int n  = g_cnt[b * 32]; if (n > CAND_MAX) n = CAND_MAX;
    int tb = g_tbin[b * 32];

    int per = (n + SLICES - 1) / SLICES;
    int lo = sl * per;
    int hi = lo + per; if (hi > n) hi = n;

    for (int p = lo + threadIdx.x; p < hi; p += blockDim.x) {
        unsigned long long pk = g_cand[b][p];
        int bin = (int)(pk >> 48);
        if (bin > tb) {
            int q = atomicAdd(&g_selcnt[b * 32], 1);
            if (q < SELCAP) g_sel[b][q] = pk;
        } else if (bin == tb) {
            int q = atomicAdd(&g_eqcnt[b * 32], 1);
            if (q < EQCAP) g_eq[b][q] = pk;
        }
    }
}

// ---------------------------------------------------------------------------
// K4: exact rank of <=K above entries + ties, gather, emit, reset counters.
__global__ void emit_kernel(const float* __restrict__ y, float* __restrict__ out) {
    int b = blockIdx.x;
    int tid = threadIdx.x;             // 256 threads

    __shared__ unsigned long long a[K];
    __shared__ unsigned long long se[EQCAP];

    int mA = g_selcnt[b * 32]; if (mA > SELCAP) mA = SELCAP; if (mA > K) mA = K;
    int nE = g_eqcnt[b * 32];  if (nE > EQCAP) nE = EQCAP;
    int take = K - mA; if (take > nE) take = nE;

    if (tid < mA) a[tid] = g_sel[b][tid];
    for (int e = tid; e < nE; e += blockDim.x) se[e] = g_eq[b][e];
    __syncthreads();

    // ties: top 'take' by (score desc, idx asc) == largest packed
    for (int e = tid; e < nE; e += blockDim.x) {
        unsigned long long mine = se[e];
        int r = 0;
        for (int q = 0; q < nE; ++q) r += (se[q] > mine) ? 1 : 0;
        if (r < take) a[mA + r] = mine;
    }
    __syncthreads();

    int M = mA + take;                 // == K normally

    float* score_out = out;
    float* k_out     = out + B * K;
    float* c_out     = out + 2 * B * K;
    float* w_out     = out + 4 * B * K;

    if (tid < M) {
        unsigned long long mine = a[tid];
        int r = 0;
        for (int q = 0; q < M; ++q) r += (a[q] > mine) ? 1 : 0;

        int fi  = (int)(~(unsigned)(mine & 0xffffffffu));
        float sc = __uint_as_float((unsigned)(mine >> 32));
        int kk  = fi % C;
        int rem = fi / C;
        int jj  = rem % W;
        int ii  = rem / W;
        const float* p = y + ((size_t)((b * H + ii) * W + jj)) * CP;
        float whx = 4.0f * (expf(p[C])     - 1.0f);
        float why = 4.0f * (expf(p[C + 1]) - 1.0f);
        float cx  = 4.0f * (float)jj + p[C + 2];
        float cy  = 4.0f * (float)ii + p[C + 3];

        score_out[b * K + r] = sc;
        k_out[b * K + r]     = (float)kk;
        c_out[(b * K + r) * 2 + 0] = cx;
        c_out[(b * K + r) * 2 + 1] = cy;
        w_out[(b * K + r) * 2 + 0] = whx;
        w_out[(b * K + r) * 2 + 1] = why;
    }

    for (int r = M + tid; r < K; r += blockDim.x) {   // degenerate pad only
        score_out[b * K + r] = 0.0f;
        k_out[b * K + r]     = 0.0f;
        c_out[(b * K + r) * 2 + 0] = 0.0f;
        c_out[(b * K + r) * 2 + 1] = 0.0f;
        w_out[(b * K + r) * 2 + 0] = 0.0f;
        w_out[(b * K + r) * 2 + 1] = 0.0f;
    }

    // reset per-replay counters (hist is zeroed in threshold_kernel)
    __syncthreads();
    if (tid == 0) {
        g_cnt[b * 32] = 0;
        g_selcnt[b * 32] = 0;
        g_eqcnt[b * 32] = 0;
    }
}

extern "C" void kernel_launch(void* const* d_in, const int* in_sizes, int n_in,
                              void* d_out, int out_size) {
    const float* yp = (const float*)d_in[0];
    float* out = (float*)d_out;

    int total = B * (H / 4) * W * (C / 4);   // 2,048,000 threads
    peaks_kernel<<<total / 256, 256>>>(yp);
    threshold_kernel<<<B, 256>>>();
    compact_kernel<<<B * SLICES, 256>>>();
    emit_kernel<<<B, 256>>>(yp, out);
}